// round 17
// baseline (speedup 1.0000x reference)
#include <cuda_runtime.h>

#define TT 1024
#define OO 512
#define DD 256
#define HH 512

__device__ float g_ht[TT * HH];   // accumulated z_t @ W1[:D]
__device__ float g_ho[OO * HH];   // accumulated z_o @ W1[D:] + b1
__device__ float g_ct[TT];        // 0.505 * <ht[t], W2>
__device__ float g_co[OO];        // 0.505 * <ho[o], W2> + b2

typedef unsigned long long u64;

__device__ __forceinline__ u64 add2(u64 a, u64 b) {
    u64 d; asm("add.rn.f32x2 %0,%1,%2;" : "=l"(d) : "l"(a), "l"(b)); return d;
}
__device__ __forceinline__ u64 fma2(u64 a, u64 b, u64 c) {
    u64 d; asm("fma.rn.f32x2 %0,%1,%2,%3;" : "=l"(d) : "l"(a), "l"(b), "l"(c)); return d;
}

// ---------------------------------------------------------------------------
// Zero out (131072 f4), g_ht (131072 f4), g_ho (65536 f4): 1280 CTAs x 256.
// ---------------------------------------------------------------------------
__global__ __launch_bounds__(256) void zero_kernel(float4* __restrict__ out4)
{
    int i = blockIdx.x * 256 + threadIdx.x;
    float4 zz = make_float4(0.f, 0.f, 0.f, 0.f);
    if (i < 131072) out4[i] = zz;
    else if (i < 262144) reinterpret_cast<float4*>(g_ht)[i - 131072] = zz;
    else reinterpret_cast<float4*>(g_ho)[i - 262144] = zz;
}

// ---------------------------------------------------------------------------
// Fused GEMM, K-SPLIT by 4 (grid.z): plane z covers k in [z*64,(z+1)*64),
// accumulating via atomicAdd into single g_ht/g_ho (pre-zeroed).
// rows [0,1024)=z_t@W1[:D], [1024,1536)=z_o@W1[D:](+b1 on z=0).
// BM=64, BN=32, BK=32, 128 threads, micro 4m x 4n, depth-2 pipelined inner.
// Grid (16,24,4)=1536 CTAs -> ~41 warps/SM.
// ---------------------------------------------------------------------------
__global__ __launch_bounds__(128) void gemm_kernel(
    const float* __restrict__ z_t, const float* __restrict__ z_o,
    const float* __restrict__ W1,  const float* __restrict__ b1)
{
    __shared__ float As[2][32][68];   // [buf][k][m]; 272B row (16B mult)
    __shared__ float Bs[2][32][36];   // [buf][k][n]; 144B row (16B mult)

    const int tid = threadIdx.x;
    const int mt  = blockIdx.y;             // 0..23
    const int n0  = blockIdx.x << 5;        // 0..480
    const int z   = blockIdx.z;             // k-plane (64 k each)
    const bool isHo = (mt >= 16);
    const int m0 = (isHo ? (mt - 16) : mt) << 6;
    const float* A = isHo ? z_o : z_t;
    const float* B = isHo ? (W1 + (u64)DD * HH) : W1;
    float* C = isHo ? g_ho : g_ht;

    const int am  = tid & 63;
    const int akh = (tid >> 6) << 4;        // 0 or 16
    const int bk = tid >> 2;
    const int bn = (tid & 3) << 3;

    const int tx = tid & 7;
    const int ty = tid >> 3;                // 0..15

    u64 acc[4][2];
    #pragma unroll
    for (int m = 0; m < 4; m++) { acc[m][0] = 0ull; acc[m][1] = 0ull; }

    const float* aptr = &A[(u64)(m0 + am) * DD + (z << 6) + akh];
    const float* bptr = &B[(u64)((z << 6) + bk) * HH + n0 + bn];

    float4 va[4], vb[2];

    // ---- prologue: stage 0 ----
    #pragma unroll
    for (int q = 0; q < 4; q++)
        va[q] = *reinterpret_cast<const float4*>(aptr + (q << 2));
    vb[0] = *reinterpret_cast<const float4*>(bptr);
    vb[1] = *reinterpret_cast<const float4*>(bptr + 4);

    #pragma unroll
    for (int q = 0; q < 4; q++) {
        As[0][akh + (q << 2) + 0][am] = va[q].x;
        As[0][akh + (q << 2) + 1][am] = va[q].y;
        As[0][akh + (q << 2) + 2][am] = va[q].z;
        As[0][akh + (q << 2) + 3][am] = va[q].w;
    }
    *reinterpret_cast<float4*>(&Bs[0][bk][bn])     = vb[0];
    *reinterpret_cast<float4*>(&Bs[0][bk][bn + 4]) = vb[1];
    __syncthreads();

    #pragma unroll 1
    for (int kb = 0; kb < 2; kb++) {        // 2 x 32 = this plane's 64 k
        const int cur = kb & 1, nxt = cur ^ 1;

        if (kb < 1) {
            const float* ap = aptr + 32;
            #pragma unroll
            for (int q = 0; q < 4; q++)
                va[q] = *reinterpret_cast<const float4*>(ap + (q << 2));
            const float* bp = bptr + (u64)32 * HH;
            vb[0] = *reinterpret_cast<const float4*>(bp);
            vb[1] = *reinterpret_cast<const float4*>(bp + 4);
        }

        // ---- depth-2 pipelined 32-k compute ----
        float4     a0 = *reinterpret_cast<const float4*>(&As[cur][0][ty << 2]);
        ulonglong2 q0 = *reinterpret_cast<const ulonglong2*>(&Bs[cur][0][tx << 2]);
        float4     a1 = *reinterpret_cast<const float4*>(&As[cur][1][ty << 2]);
        ulonglong2 q1 = *reinterpret_cast<const ulonglong2*>(&Bs[cur][1][tx << 2]);

        #pragma unroll
        for (int k = 0; k < 32; k++) {
            float4 a2; ulonglong2 q2;
            if (k < 30) {
                a2 = *reinterpret_cast<const float4*>(&As[cur][k + 2][ty << 2]);
                q2 = *reinterpret_cast<const ulonglong2*>(&Bs[cur][k + 2][tx << 2]);
            }
            u64 ad0, ad1, ad2, ad3;
            asm("mov.b64 %0,{%1,%1};" : "=l"(ad0) : "f"(a0.x));
            asm("mov.b64 %0,{%1,%1};" : "=l"(ad1) : "f"(a0.y));
            asm("mov.b64 %0,{%1,%1};" : "=l"(ad2) : "f"(a0.z));
            asm("mov.b64 %0,{%1,%1};" : "=l"(ad3) : "f"(a0.w));
            acc[0][0] = fma2(ad0, q0.x, acc[0][0]);
            acc[0][1] = fma2(ad0, q0.y, acc[0][1]);
            acc[1][0] = fma2(ad1, q0.x, acc[1][0]);
            acc[1][1] = fma2(ad1, q0.y, acc[1][1]);
            acc[2][0] = fma2(ad2, q0.x, acc[2][0]);
            acc[2][1] = fma2(ad2, q0.y, acc[2][1]);
            acc[3][0] = fma2(ad3, q0.x, acc[3][0]);
            acc[3][1] = fma2(ad3, q0.y, acc[3][1]);
            a0 = a1; q0 = q1;
            a1 = a2; q1 = q2;
        }

        if (kb < 1) {
            #pragma unroll
            for (int q = 0; q < 4; q++) {
                As[nxt][akh + (q << 2) + 0][am] = va[q].x;
                As[nxt][akh + (q << 2) + 1][am] = va[q].y;
                As[nxt][akh + (q << 2) + 2][am] = va[q].z;
                As[nxt][akh + (q << 2) + 3][am] = va[q].w;
            }
            *reinterpret_cast<float4*>(&Bs[nxt][bk][bn])     = vb[0];
            *reinterpret_cast<float4*>(&Bs[nxt][bk][bn + 4]) = vb[1];
            __syncthreads();
        }
    }

    // epilogue: atomic accumulate; bias only on plane 0
    float4 bv = make_float4(0.f, 0.f, 0.f, 0.f);
    if (isHo && z == 0) bv = *reinterpret_cast<const float4*>(&b1[n0 + (tx << 2)]);

    #pragma unroll
    for (int m = 0; m < 4; m++) {
        float2 p0 = *reinterpret_cast<float2*>(&acc[m][0]);
        float2 p1 = *reinterpret_cast<float2*>(&acc[m][1]);
        int row = m0 + (ty << 2) + m;
        float* cp = &C[(u64)row * HH + n0 + (tx << 2)];
        atomicAdd(cp + 0, p0.x + bv.x);
        atomicAdd(cp + 1, p0.y + bv.y);
        atomicAdd(cp + 2, p1.x + bv.z);
        atomicAdd(cp + 3, p1.y + bv.w);
    }
}

// ---------------------------------------------------------------------------
// Per-row linear terms: ct[t] = 0.505*<ht[t],W2>, co[o] = 0.505*<ho[o],W2>+b2
// ---------------------------------------------------------------------------
__global__ __launch_bounds__(256) void reduce_kernel(
    const float* __restrict__ W2, const float* __restrict__ b2)
{
    int warp = (blockIdx.x * blockDim.x + threadIdx.x) >> 5;
    int lane = threadIdx.x & 31;
    const float* row;
    float* dst;
    float extra = 0.f;
    if (warp < TT) { row = g_ht + (u64)warp * HH; dst = g_ct + warp; }
    else { row = g_ho + (u64)(warp - TT) * HH; dst = g_co + (warp - TT); extra = b2[0]; }
    float s = 0.f;
    #pragma unroll
    for (int i = 0; i < 4; i++) {
        float4 v = *reinterpret_cast<const float4*>(&row[(lane + 32 * i) << 2]);
        float4 w = *reinterpret_cast<const float4*>(&W2[(lane + 32 * i) << 2]);
        s += v.x * w.x + v.y * w.y + v.z * w.z + v.w * w.w;
    }
    #pragma unroll
    for (int off = 16; off; off >>= 1) s += __shfl_xor_sync(0xffffffffu, s, off);
    if (lane == 0) *dst = 0.505f * s + extra;
}

// ---------------------------------------------------------------------------
// Pairwise kernel, H-SPLIT by 4 (grid.z): plane z covers h [z*128,(z+1)*128)
// = 2 chunks of 64. All planes atomicAdd into pre-zeroed out; z=0 adds ct+co.
// 64x64 tile, 256 threads, micro 4t x 4o. Grid (8,16,4)=512 CTAs, ~6 w/SMSP.
// No explicit pipelining (warp count hides latency; keeps regs low).
// ---------------------------------------------------------------------------
__global__ __launch_bounds__(256) void pair_kernel(
    const float* __restrict__ W2, float* __restrict__ out)
{
    __shared__ float4 sA[16][65];      // [hq][t], float4 = 4 h
    __shared__ float4 sB[16][65];      // [hq][o]
    __shared__ float4 sW[HH / 4];      // 0.495*W2 quads

    const int tid = threadIdx.x;
    const int tx = tid & 15;           // o lane (o = tx + 16j)
    const int ty = tid >> 4;           // t lane (t = ty + 16i)
    const int t0 = blockIdx.y << 6;
    const int o0 = blockIdx.x << 6;
    const int z  = blockIdx.z;         // h-quarter
    const int cz = z << 1;             // first chunk (of 64 h) in this quarter

    if (tid < HH / 4) {
        float4 w = *reinterpret_cast<const float4*>(&W2[tid << 2]);
        w.x *= 0.495f; w.y *= 0.495f; w.z *= 0.495f; w.w *= 0.495f;
        sW[tid] = w;
    }

    u64 acc[4][4];
    #pragma unroll
    for (int i = 0; i < 4; i++)
        #pragma unroll
        for (int j = 0; j < 4; j++) acc[i][j] = 0ull;

    const int hs = tid & 15;           // hq for staging
    const int ts = tid >> 4;           // 0..15
    const u64 SMASK = 0x7fffffff7fffffffULL;

    #pragma unroll 1
    for (int cc = 0; cc < 2; cc++) {   // 2 chunks of 64 h in this quarter
        const int c = cz + cc;
        const int hoff = (c << 6) + (hs << 2);
        #pragma unroll
        for (int r = 0; r < 4; r++) {
            sA[hs][ts + (r << 4)] =
                *reinterpret_cast<const float4*>(&g_ht[(u64)(t0 + ts + (r << 4)) * HH + hoff]);
            sB[hs][ts + (r << 4)] =
                *reinterpret_cast<const float4*>(&g_ho[(u64)(o0 + ts + (r << 4)) * HH + hoff]);
        }
        __syncthreads();

        #pragma unroll
        for (int hq = 0; hq < 16; hq++) {
            ulonglong2 w = *reinterpret_cast<const ulonglong2*>(&sW[(c << 4) + hq]);
            ulonglong2 a[4], b[4];
            #pragma unroll
            for (int i = 0; i < 4; i++)
                a[i] = *reinterpret_cast<const ulonglong2*>(&sA[hq][ty + (i << 4)]);
            #pragma unroll
            for (int j = 0; j < 4; j++)
                b[j] = *reinterpret_cast<const ulonglong2*>(&sB[hq][tx + (j << 4)]);
            #pragma unroll
            for (int i = 0; i < 4; i++)
                #pragma unroll
                for (int j = 0; j < 4; j++) {
                    u64 x = add2(a[i].x, b[j].x) & SMASK;
                    acc[i][j] = fma2(x, w.x, acc[i][j]);
                    u64 y = add2(a[i].y, b[j].y) & SMASK;
                    acc[i][j] = fma2(y, w.y, acc[i][j]);
                }
        }
        __syncthreads();
    }

    float ctv[4], cov[4];
    if (z == 0) {
        #pragma unroll
        for (int i = 0; i < 4; i++) ctv[i] = g_ct[t0 + ty + (i << 4)];
        #pragma unroll
        for (int j = 0; j < 4; j++) cov[j] = g_co[o0 + tx + (j << 4)];
    } else {
        #pragma unroll
        for (int i = 0; i < 4; i++) ctv[i] = 0.f;
        #pragma unroll
        for (int j = 0; j < 4; j++) cov[j] = 0.f;
    }
    #pragma unroll
    for (int i = 0; i < 4; i++)
        #pragma unroll
        for (int j = 0; j < 4; j++) {
            float2 p = *reinterpret_cast<float2*>(&acc[i][j]);
            atomicAdd(&out[(u64)(t0 + ty + (i << 4)) * OO + o0 + tx + (j << 4)],
                      ctv[i] + cov[j] + p.x + p.y);
        }
}

extern "C" void kernel_launch(void* const* d_in, const int* in_sizes, int n_in,
                              void* d_out, int out_size)
{
    const float* z_t = (const float*)d_in[0];   // [1024,256]
    const float* z_o = (const float*)d_in[1];   // [512,256]
    const float* W1  = (const float*)d_in[2];   // [512,512]
    const float* b1  = (const float*)d_in[3];   // [512]
    const float* W2  = (const float*)d_in[4];   // [512,1]
    const float* b2  = (const float*)d_in[5];   // [1]
    float* out = (float*)d_out;                 // [1024,512]

    zero_kernel<<<1280, 256>>>((float4*)out);
    gemm_kernel<<<dim3(16, 24, 4), 128>>>(z_t, z_o, W1, b1);
    reduce_kernel<<<192, 256>>>(W2, b2);
    pair_kernel<<<dim3(OO / 64, TT / 64, 4), 256>>>(W2, out);
}